// round 15
// baseline (speedup 1.0000x reference)
#include <cuda_runtime.h>
#include <cuda_fp16.h>
#include <cstdint>

#define DEV_INLINE __device__ __forceinline__

constexpr int N  = 131072;
constexpr int C  = 128;
constexpr int S  = 6;
constexpr int E  = 131072;
constexpr int EL = 32768;
constexpr int NB = 4;
constexpr int CC = C * C;
constexpr int NSLOT = 66;
constexpr int NT = 1024;   // source row tiles (N/128)
constexpr int NLS = 12;    // sorted edge lists: 0-5 pre, 6-11 suc
constexpr int ESTORE = 12 * E;
constexpr int IDX_CAP = 512;   // smem-resident edges per (tile, list)
constexpr int NCHUNK = EL / 128;  // 256 compact chunks for left/right

// Scratch (allocation-free rule: static __device__ arrays)
__device__ float  g_feat[N * C];
__device__ float  g_temp[N * C];
__device__ float  g_Y[N * C];
__device__ __half g_A[N * C];           // fp16 activations
__device__ __half g_Wh[NSLOT * CC];     // fp16 weights, [slot][c][k] (transposed)
// edge sort scratch
__device__ int g_cnt[NLS * NT];
__device__ int g_off[NLS * (NT + 1)];
__device__ int g_epk[ESTORE];  // packed edge: (u << 7) | (v & 127)

DEV_INLINE uint32_t smem_u32(const void* p) {
  uint32_t a;
  asm("{ .reg .u64 t; cvta.to.shared.u64 t, %1; cvt.u32.u64 %0, t; }"
      : "=r"(a) : "l"(p));
  return a;
}

// ---------------------------------------------------------------------------
// MMA building blocks. smem tile: 128 rows x 256B, XOR-16B swizzle on (row&7)
// ---------------------------------------------------------------------------
constexpr int TILE_BYTES = 128 * 256;  // 32 KB (128x128 fp16)

DEV_INLINE void ldsm4(uint32_t& r0, uint32_t& r1, uint32_t& r2, uint32_t& r3,
                      uint32_t addr) {
  asm volatile("ldmatrix.sync.aligned.m8n8.x4.shared.b16 {%0,%1,%2,%3}, [%4];"
               : "=r"(r0), "=r"(r1), "=r"(r2), "=r"(r3) : "r"(addr));
}
DEV_INLINE void mma_f16(float* c, uint32_t a0, uint32_t a1, uint32_t a2,
                        uint32_t a3, uint32_t b0, uint32_t b1) {
  asm volatile(
      "mma.sync.aligned.m16n8k16.row.col.f32.f16.f16.f32 "
      "{%0,%1,%2,%3}, {%4,%5,%6,%7}, {%8,%9}, {%0,%1,%2,%3};"
      : "+f"(c[0]), "+f"(c[1]), "+f"(c[2]), "+f"(c[3])
      : "r"(a0), "r"(a1), "r"(a2), "r"(a3), "r"(b0), "r"(b1));
}

DEV_INLINE void cp_async16(uint32_t dst, const void* src) {
  asm volatile("cp.async.cg.shared.global [%0], [%1], 16;" :: "r"(dst),
               "l"(src));
}
DEV_INLINE void cp_async4(uint32_t dst, const void* src) {
  asm volatile("cp.async.ca.shared.global [%0], [%1], 4;" :: "r"(dst),
               "l"(src));
}
#define CP_COMMIT() asm volatile("cp.async.commit_group;" ::: "memory")
#define CP_WAIT(n)  asm volatile("cp.async.wait_group %0;" :: "n"(n) : "memory")

// stage one 128x128 fp16 tile (32 KB) with swizzle via cp.async; 256 threads
DEV_INLINE void stage_async(uint32_t dstBase, const __half* src, int tid) {
  const char* s = (const char*)src;
#pragma unroll
  for (int t = 0; t < 8; ++t) {
    int idx = tid + t * 256;
    int r = idx >> 4, c16 = idx & 15;
    uint32_t off = r * 256 + ((c16 * 16) ^ ((r & 7) << 4));
    cp_async16(dstBase + off, s + idx * 16);
  }
}

// fragment address precompute
struct FragIdx {
  uint32_t aRow[4], aColK, bRow[2], bColK;
  int rw, cw;
};
DEV_INLINE FragIdx frag_idx(int lane, int wid) {
  FragIdx f;
  f.rw = (wid & 1) * 64;
  f.cw = (wid >> 1) * 32;
  f.aColK = (lane >> 4) * 16;
#pragma unroll
  for (int mi = 0; mi < 4; ++mi) f.aRow[mi] = f.rw + mi * 16 + (lane & 15);
  f.bColK = ((lane >> 3) & 1) * 16;
#pragma unroll
  for (int bi = 0; bi < 2; ++bi)
    f.bRow[bi] = f.cw + bi * 16 + ((lane >> 4) * 8) + (lane & 7);
  return f;
}

DEV_INLINE void zero_acc(float (&acc)[4][4][4]) {
#pragma unroll
  for (int mi = 0; mi < 4; ++mi)
#pragma unroll
    for (int ni = 0; ni < 4; ++ni)
#pragma unroll
      for (int j = 0; j < 4; ++j) acc[mi][ni][j] = 0.0f;
}

// one K-sweep (8 chunks) of A@B accumulated
DEV_INLINE void mma_pass(uint32_t aBase, uint32_t bBase, const FragIdx& f,
                         float (&acc)[4][4][4]) {
#pragma unroll
  for (int kk = 0; kk < 8; ++kk) {
    const uint32_t kb = kk * 32;
    uint32_t a[4][4];
#pragma unroll
    for (int mi = 0; mi < 4; ++mi) {
      uint32_t r = f.aRow[mi];
      uint32_t addr = aBase + r * 256 + ((kb | f.aColK) ^ ((r & 7) << 4));
      ldsm4(a[mi][0], a[mi][1], a[mi][2], a[mi][3], addr);
    }
    uint32_t b[4][2];
#pragma unroll
    for (int bi = 0; bi < 2; ++bi) {
      uint32_t r = f.bRow[bi];
      uint32_t addr = bBase + r * 256 + ((kb | f.bColK) ^ ((r & 7) << 4));
      ldsm4(b[bi * 2][0], b[bi * 2][1], b[bi * 2 + 1][0], b[bi * 2 + 1][1],
            addr);
    }
#pragma unroll
    for (int mi = 0; mi < 4; ++mi)
#pragma unroll
      for (int ni = 0; ni < 4; ++ni)
        mma_f16(acc[mi][ni], a[mi][0], a[mi][1], a[mi][2], a[mi][3],
                b[ni][0], b[ni][1]);
  }
}

// stage accumulators as fp32 into smem at base: 128 rows x 512B, XOR swizzle
DEV_INLINE void stage_acc_smem(char* base, int lane, int wid,
                               float (&acc)[4][4][4]) {
  const int rw = (wid & 1) * 64, cw = (wid >> 1) * 32;
  const int r0 = lane >> 2, c0 = (lane & 3) * 2;
#pragma unroll
  for (int mi = 0; mi < 4; ++mi)
#pragma unroll
    for (int ni = 0; ni < 4; ++ni) {
      int row = rw + mi * 16 + r0, col = cw + ni * 8 + c0;
      uint32_t o1 = row * 512 + ((col * 4) ^ ((row & 7) << 4));
      *(float2*)(base + o1) = make_float2(acc[mi][ni][0], acc[mi][ni][1]);
      uint32_t o2 = (row + 8) * 512 + ((col * 4) ^ (((row + 8) & 7) << 4));
      *(float2*)(base + o2) = make_float2(acc[mi][ni][2], acc[mi][ni][3]);
    }
}

DEV_INLINE float wsum(float v) {
#pragma unroll
  for (int o = 16; o > 0; o >>= 1) v += __shfl_xor_sync(0xffffffffu, v, o);
  return v;
}

// mlp layer-0 prologue: relu(x@W0 + b0) for this CTA's 128 rows -> fp16 A tile
DEV_INLINE void mlp0_prologue(char* smem, const float* X2, const float* W0,
                              const float* B0, int rowBase, int lane, int wid) {
  float4 wa = *(const float4*)(W0 + lane * 4);
  float4 wb = *(const float4*)(W0 + C + lane * 4);
  float4 b0 = *(const float4*)(B0 + lane * 4);
#pragma unroll 4
  for (int i = 0; i < 16; ++i) {
    int r = wid * 16 + i;
    float2 x = *(const float2*)(X2 + 2 * (size_t)(rowBase + r));
    float ox = fmaxf(fmaf(x.x, wa.x, fmaf(x.y, wb.x, b0.x)), 0.0f);
    float oy = fmaxf(fmaf(x.x, wa.y, fmaf(x.y, wb.y, b0.y)), 0.0f);
    float oz = fmaxf(fmaf(x.x, wa.z, fmaf(x.y, wb.z, b0.z)), 0.0f);
    float ow = fmaxf(fmaf(x.x, wa.w, fmaf(x.y, wb.w, b0.w)), 0.0f);
    __half2 h0 = __floats2half2_rn(ox, oy);
    __half2 h1 = __floats2half2_rn(oz, ow);
    uint32_t off = r * 256 + ((lane * 8) ^ ((r & 7) << 4));
    *(uint2*)(smem + off) = make_uint2(*(uint32_t*)&h0, *(uint32_t*)&h1);
  }
}

// ---------------------------------------------------------------------------
// input stage, fully fused (one kernel, 128 KB smem, 1 CTA/SM):
//  phase1: A1 = relu(ctrs@icw0+icb0); Y1 = A1@Wh[0]  -> fp32 smem @64K
//  phase2: A2 = relu(feats@ifw0+ifb0); Y2 = A2@Wh[1] -> fp32 smem @0
//  epilogue: feat = relu(GN1(Y1)+GN2(Y2)); write FT fp32 + AA fp16 + zero TP
// ---------------------------------------------------------------------------
constexpr int SMEM_INPUT = 4 * TILE_BYTES;  // 128 KB

__global__ void __launch_bounds__(256, 1) input_fused_kernel(
    const float* __restrict__ ctrs, const float* __restrict__ ic_w0,
    const float* __restrict__ ic_b0, const float* __restrict__ feats,
    const float* __restrict__ if_w0, const float* __restrict__ if_b0,
    const __half* __restrict__ Wh01,
    const float* __restrict__ G1v, const float* __restrict__ B1v,
    const float* __restrict__ G2v, const float* __restrict__ B2v,
    float* __restrict__ OutF, __half* __restrict__ Aout,
    float* __restrict__ TPz) {
  extern __shared__ __align__(16) char smem[];
  const uint32_t sbase = smem_u32(smem);
  const int tid = threadIdx.x, lane = tid & 31, wid = tid >> 5;
  const int rowBase = blockIdx.x * 128;
  FragIdx f = frag_idx(lane, wid);

  // ---- phase 1: ctrs branch ----
  stage_async(sbase + TILE_BYTES, Wh01, tid);
  CP_COMMIT();
  mlp0_prologue(smem, ctrs, ic_w0, ic_b0, rowBase, lane, wid);
  CP_WAIT(0);
  __syncthreads();

  float acc[4][4][4];
  zero_acc(acc);
  mma_pass(sbase, sbase + TILE_BYTES, f, acc);
  __syncthreads();                       // A + W1 fully consumed
  stage_acc_smem(smem + 2 * TILE_BYTES, lane, wid, acc);  // Y1 @64K

  // ---- phase 2: feats branch ----
  stage_async(sbase + TILE_BYTES, Wh01 + CC, tid);
  CP_COMMIT();
  mlp0_prologue(smem, feats, if_w0, if_b0, rowBase, lane, wid);
  CP_WAIT(0);
  __syncthreads();                       // also covers Y1 staging visibility

  zero_acc(acc);
  mma_pass(sbase, sbase + TILE_BYTES, f, acc);
  __syncthreads();                       // A + W2 fully consumed
  stage_acc_smem(smem, lane, wid, acc);  // Y2 @0
  __syncthreads();

  // ---- epilogue: combine ----
#pragma unroll 2
  for (int i = 0; i < 16; ++i) {
    int r = wid * 16 + i;
    float4 y2 = *(float4*)(smem + r * 512 + lane * 16);
    float4 y1 = *(float4*)(smem + 2 * TILE_BYTES + r * 512 + lane * 16);
    int colb = ((lane * 16) ^ ((r & 7) << 4)) >> 2;  // logical column
    size_t goff = (size_t)(rowBase + r) * C + colb;
    float s1 = wsum(y1.x + y1.y + y1.z + y1.w);
    float q1 = wsum(y1.x * y1.x + y1.y * y1.y + y1.z * y1.z + y1.w * y1.w);
    float s2 = wsum(y2.x + y2.y + y2.z + y2.w);
    float q2 = wsum(y2.x * y2.x + y2.y * y2.y + y2.z * y2.z + y2.w * y2.w);
    float mu1 = s1 * (1.0f / 128.0f);
    float rs1 = rsqrtf(q1 * (1.0f / 128.0f) - mu1 * mu1 + 1e-5f);
    float mu2 = s2 * (1.0f / 128.0f);
    float rs2 = rsqrtf(q2 * (1.0f / 128.0f) - mu2 * mu2 + 1e-5f);
    float4 g1 = *(const float4*)(G1v + colb);
    float4 b1 = *(const float4*)(B1v + colb);
    float4 g2 = *(const float4*)(G2v + colb);
    float4 b2 = *(const float4*)(B2v + colb);
    float4 o;
    o.x = fmaxf((y1.x - mu1) * rs1 * g1.x + b1.x + (y2.x - mu2) * rs2 * g2.x + b2.x, 0.0f);
    o.y = fmaxf((y1.y - mu1) * rs1 * g1.y + b1.y + (y2.y - mu2) * rs2 * g2.y + b2.y, 0.0f);
    o.z = fmaxf((y1.z - mu1) * rs1 * g1.z + b1.z + (y2.z - mu2) * rs2 * g2.z + b2.z, 0.0f);
    o.w = fmaxf((y1.w - mu1) * rs1 * g1.w + b1.w + (y2.w - mu2) * rs2 * g2.w + b2.w, 0.0f);
    *(float4*)(OutF + goff) = o;
    __half2 h0 = __floats2half2_rn(o.x, o.y);
    __half2 h1 = __floats2half2_rn(o.z, o.w);
    *(uint2*)(Aout + goff) = make_uint2(*(uint32_t*)&h0, *(uint32_t*)&h1);
    *(float4*)(TPz + goff) = make_float4(0.f, 0.f, 0.f, 0.f);
  }
}

// ---------------------------------------------------------------------------
// fused block tail: prologue GN(temp)+relu -> fp16 A tile, single-pass ctr2
// MMA, epilogue rowwise GN + identity + relu. Y2 fp32 staged at base 0.
// 64 KB smem, 2 CTA/SM.
// ---------------------------------------------------------------------------
constexpr int SMEM_TAIL = 2 * TILE_BYTES;  // 64 KB

__global__ void __launch_bounds__(256, 2) gn_gemm_gn_kernel(
    const float* __restrict__ Xin,
    const float* __restrict__ G1v, const float* __restrict__ B1v,
    const __half* __restrict__ Bh,
    const float* __restrict__ G2v, const float* __restrict__ B2v,
    const float* __restrict__ Id, float* __restrict__ OutF,
    __half* __restrict__ Aout, float* __restrict__ TPz) {
  extern __shared__ __align__(16) char smem[];
  const uint32_t sbase = smem_u32(smem);
  const int tid = threadIdx.x, lane = tid & 31, wid = tid >> 5;
  const int rowBase = blockIdx.x * 128;

  stage_async(sbase + TILE_BYTES, Bh, tid);
  CP_COMMIT();

  {
    float4 g1 = ((const float4*)G1v)[lane];
    float4 b1 = ((const float4*)B1v)[lane];
#pragma unroll 4
    for (int i = 0; i < 16; ++i) {
      int r = wid * 16 + i;
      float4 x = *(const float4*)(Xin + (size_t)(rowBase + r) * C + lane * 4);
      float s = wsum(x.x + x.y + x.z + x.w);
      float q = wsum(x.x * x.x + x.y * x.y + x.z * x.z + x.w * x.w);
      float mu = s * (1.0f / 128.0f);
      float rs = rsqrtf(q * (1.0f / 128.0f) - mu * mu + 1e-5f);
      float ox = fmaxf((x.x - mu) * rs * g1.x + b1.x, 0.0f);
      float oy = fmaxf((x.y - mu) * rs * g1.y + b1.y, 0.0f);
      float oz = fmaxf((x.z - mu) * rs * g1.z + b1.z, 0.0f);
      float ow = fmaxf((x.w - mu) * rs * g1.w + b1.w, 0.0f);
      __half2 h0 = __floats2half2_rn(ox, oy);
      __half2 h1 = __floats2half2_rn(oz, ow);
      uint32_t off = r * 256 + ((lane * 8) ^ ((r & 7) << 4));
      *(uint2*)(smem + off) = make_uint2(*(uint32_t*)&h0, *(uint32_t*)&h1);
    }
  }
  CP_WAIT(0);
  __syncthreads();

  FragIdx f = frag_idx(lane, wid);
  float acc[4][4][4];
  zero_acc(acc);
  mma_pass(sbase, sbase + TILE_BYTES, f, acc);
  __syncthreads();

  stage_acc_smem(smem, lane, wid, acc);  // Y2 fp32 at base 0
  __syncthreads();

#pragma unroll 2
  for (int i = 0; i < 16; ++i) {
    int r = wid * 16 + i;
    float4 y = *(float4*)(smem + r * 512 + lane * 16);
    float s = wsum(y.x + y.y + y.z + y.w);
    float q = wsum(y.x * y.x + y.y * y.y + y.z * y.z + y.w * y.w);
    float mu = s * (1.0f / 128.0f);
    float rs = rsqrtf(q * (1.0f / 128.0f) - mu * mu + 1e-5f);
    int colb = ((lane * 16) ^ ((r & 7) << 4)) >> 2;
    float4 g2 = *(const float4*)(G2v + colb);
    float4 b2 = *(const float4*)(B2v + colb);
    size_t goff = (size_t)(rowBase + r) * C + colb;
    float4 id = *(const float4*)(Id + goff);
    float4 o;
    o.x = fmaxf((y.x - mu) * rs * g2.x + b2.x + id.x, 0.0f);
    o.y = fmaxf((y.y - mu) * rs * g2.y + b2.y + id.y, 0.0f);
    o.z = fmaxf((y.z - mu) * rs * g2.z + b2.z + id.z, 0.0f);
    o.w = fmaxf((y.w - mu) * rs * g2.w + b2.w + id.w, 0.0f);
    *(float4*)(OutF + goff) = o;
    if (Aout) {
      __half2 h0 = __floats2half2_rn(o.x, o.y);
      __half2 h1 = __floats2half2_rn(o.z, o.w);
      *(uint2*)(Aout + goff) = make_uint2(*(uint32_t*)&h0, *(uint32_t*)&h1);
    }
    if (TPz) *(float4*)(TPz + goff) = make_float4(0.f, 0.f, 0.f, 0.f);
  }
}

// ---------------------------------------------------------------------------
// fused per-block kernel (unchanged structure from R13/R14)
// ---------------------------------------------------------------------------
constexpr int YPITCH_H = 136;
constexpr int W_OFF   = TILE_BYTES;       // 32768
constexpr int Y_OFF   = 2 * TILE_BYTES;   // 65536
constexpr int IDX_OFF = Y_OFF + 128 * YPITCH_H * 2;      // 100352
constexpr int CMP_OFF = IDX_OFF + 2 * IDX_CAP * 4;       // 104448
constexpr int SMEM_FUSED = CMP_OFF + 4 * 128 * 4;        // 106496

__global__ void __launch_bounds__(256, 2) fused_block_kernel(
    const __half* __restrict__ A, int ib, float* __restrict__ TP,
    const int* __restrict__ left_u, const int* __restrict__ left_v,
    const int* __restrict__ right_u, const int* __restrict__ right_v) {
  extern __shared__ __align__(16) char smem[];
  const uint32_t sbase = smem_u32(smem);
  __half* Ybuf = (__half*)(smem + Y_OFF);
  const int tid = threadIdx.x, lane = tid & 31, wid = tid >> 5;
  const int rowBase = blockIdx.x * 128;
  const bool activeCmp = blockIdx.x < NCHUNK;
  const int itMax = activeCmp ? 15 : 13;

  const int rw = (wid & 1) * 64, cw = (wid >> 1) * 32;
  const int r0 = lane >> 2, c0 = (lane & 3) * 2;

  auto slot_of = [&](int it) {
    return (it == 0)   ? 2 + ib
           : (it < 7)  ? 6 + ib * 6 + (it - 1)
           : (it < 13) ? 30 + ib * 6 + (it - 7)
           : (it == 13) ? 54 + ib : 58 + ib;
  };
  auto ebase_of = [&](int it) { return (it - 1) * E; };
  auto stage_idx = [&](int it) {
    int l = it - 1;
    int o0 = g_off[l * (NT + 1) + blockIdx.x];
    int o1 = g_off[l * (NT + 1) + blockIdx.x + 1];
    int cnt = min(o1 - o0, IDX_CAP);
    const int* src = g_epk + ebase_of(it) + o0;
    uint32_t dst = sbase + IDX_OFF + (it & 1) * (IDX_CAP * 4);
    for (int j = tid; j < cnt; j += 256) cp_async4(dst + j * 4, src + j);
  };
  auto stage_gather = [&](int voff) {
    const int* vs = (const int*)(smem + CMP_OFF + voff);
#pragma unroll
    for (int t2 = 0; t2 < 8; ++t2) {
      int idx = tid + t2 * 256;
      int row = idx >> 4, c16 = idx & 15;
      int vrow = vs[row];
      uint32_t off = row * 256 + ((c16 * 16) ^ ((row & 7) << 4));
      cp_async16(sbase + off, A + (size_t)vrow * C + c16 * 8);
    }
  };

  stage_async(sbase, A + (size_t)rowBase * C, tid);
  stage_async(sbase + W_OFF, g_Wh + (size_t)slot_of(0) * CC, tid);
  stage_idx(1);
  if (activeCmp) {
    int cb = blockIdx.x * 128;
    for (int j = tid; j < 128; j += 256) {
      cp_async4(sbase + CMP_OFF + j * 4, left_u + cb + j);
      cp_async4(sbase + CMP_OFF + 512 + j * 4, left_v + cb + j);
      cp_async4(sbase + CMP_OFF + 1024 + j * 4, right_u + cb + j);
      cp_async4(sbase + CMP_OFF + 1536 + j * 4, right_v + cb + j);
    }
  }
  CP_COMMIT();
  CP_WAIT(0);
  __syncthreads();

  FragIdx f = frag_idx(lane, wid);

#pragma unroll 1
  for (int it = 0; it < itMax; ++it) {
    float acc[4][4][4];
    zero_acc(acc);
    mma_pass(sbase, sbase + W_OFF, f, acc);

#pragma unroll
    for (int mi = 0; mi < 4; ++mi)
#pragma unroll
      for (int ni = 0; ni < 4; ++ni) {
        int row = rw + mi * 16 + r0, col = cw + ni * 8 + c0;
        __half2 h0 = __floats2half2_rn(acc[mi][ni][0], acc[mi][ni][1]);
        __half2 h1 = __floats2half2_rn(acc[mi][ni][2], acc[mi][ni][3]);
        *(__half2*)(Ybuf + row * YPITCH_H + col) = h0;
        *(__half2*)(Ybuf + (row + 8) * YPITCH_H + col) = h1;
      }
    __syncthreads();  // Ybuf ready; W(it) + A region fully consumed

    if (it + 1 < itMax) {
      stage_async(sbase + W_OFF, g_Wh + (size_t)slot_of(it + 1) * CC, tid);
      if (it + 1 <= 12) stage_idx(it + 1);
      else stage_gather(it + 1 == 13 ? 512 : 1536);
      CP_COMMIT();
    }

    if (it == 0) {
      for (int r = wid; r < 128; r += 8) {
        uint2 hv = *(uint2*)(Ybuf + r * YPITCH_H + lane * 4);
        float2 f0 = __half22float2(*(__half2*)&hv.x);
        float2 f1 = __half22float2(*(__half2*)&hv.y);
        float* p = TP + (size_t)(rowBase + r) * C + lane * 4;
        asm volatile("red.global.add.v4.f32 [%0], {%1,%2,%3,%4};"
                     :: "l"(p), "f"(f0.x), "f"(f0.y), "f"(f1.x), "f"(f1.y)
                     : "memory");
      }
    } else if (it <= 12) {
      int l = it - 1;
      int o0 = g_off[l * (NT + 1) + blockIdx.x];
      int o1 = g_off[l * (NT + 1) + blockIdx.x + 1];
      int cnt = o1 - o0;
      const int* sidx = (const int*)(smem + IDX_OFF + (it & 1) * (IDX_CAP * 4));
      const int* gidx = g_epk + ebase_of(it) + o0;
#pragma unroll 2
      for (int j = wid; j < cnt; j += 8) {
        int pk = (j < IDX_CAP) ? sidx[j] : __ldg(&gidx[j]);
        int vl = pk & 127;
        int uu = pk >> 7;
        uint2 hv = *(uint2*)(Ybuf + vl * YPITCH_H + lane * 4);
        float2 f0 = __half22float2(*(__half2*)&hv.x);
        float2 f1 = __half22float2(*(__half2*)&hv.y);
        float* p = TP + (size_t)uu * C + lane * 4;
        asm volatile("red.global.add.v4.f32 [%0], {%1,%2,%3,%4};"
                     :: "l"(p), "f"(f0.x), "f"(f0.y), "f"(f1.x), "f"(f1.y)
                     : "memory");
      }
    } else {
      const int* uarr = (const int*)(smem + CMP_OFF + (it == 13 ? 0 : 1024));
      for (int r = wid; r < 128; r += 8) {
        int uu = uarr[r];
        uint2 hv = *(uint2*)(Ybuf + r * YPITCH_H + lane * 4);
        float2 f0 = __half22float2(*(__half2*)&hv.x);
        float2 f1 = __half22float2(*(__half2*)&hv.y);
        float* p = TP + (size_t)uu * C + lane * 4;
        asm volatile("red.global.add.v4.f32 [%0], {%1,%2,%3,%4};"
                     :: "l"(p), "f"(f0.x), "f"(f0.y), "f"(f1.x), "f"(f1.y)
                     : "memory");
      }
    }

    if (it + 1 < itMax) CP_WAIT(0);
    __syncthreads();
  }
}

// ---------------------------------------------------------------------------
// edge sort (counting sort by v>>7) for the 12 pre/suc lists.
// prefix_kernel also leaves fill cursors (exclusive offsets) in g_cnt.
// ---------------------------------------------------------------------------
__global__ void zero_cnt_kernel() {
  int i = blockIdx.x * 256 + threadIdx.x;
  if (i < NLS * NT) g_cnt[i] = 0;
}
__global__ void hist_all_kernel(const int* __restrict__ pre_v,
                                const int* __restrict__ suc_v) {
  int e = blockIdx.x * 256 + threadIdx.x;
  if (e >= 12 * E) return;
  int l = e / E;
  const int* vp = (l < 6) ? pre_v : suc_v;
  int off = (l < 6) ? e : e - 6 * E;
  atomicAdd(&g_cnt[l * NT + (__ldg(&vp[off]) >> 7)], 1);
}
__global__ void prefix_kernel() {  // one block per list, 1024 threads
  __shared__ int sh[NT];
  int l = blockIdx.x, t = threadIdx.x;
  int myc = g_cnt[l * NT + t];
  sh[t] = myc;
  __syncthreads();
#pragma unroll
  for (int d = 1; d < NT; d <<= 1) {
    int x = (t >= d) ? sh[t - d] : 0;
    __syncthreads();
    sh[t] += x;
    __syncthreads();
  }
  g_off[l * (NT + 1) + t + 1] = sh[t];
  if (t == 0) g_off[l * (NT + 1)] = 0;
  g_cnt[l * NT + t] = sh[t] - myc;  // exclusive offset = fill cursor
}
__global__ void fill_all_kernel(const int* __restrict__ pre_u,
                                const int* __restrict__ pre_v,
                                const int* __restrict__ suc_u,
                                const int* __restrict__ suc_v) {
  int e = blockIdx.x * 256 + threadIdx.x;
  if (e >= 12 * E) return;
  int l = e / E;
  const int* vp = (l < 6) ? pre_v : suc_v;
  const int* up = (l < 6) ? pre_u : suc_u;
  int off = (l < 6) ? e : e - 6 * E;
  int vv = __ldg(&vp[off]);
  int t = vv >> 7;
  int pos = l * E + atomicAdd(&g_cnt[l * NT + t], 1);
  g_epk[pos] = (__ldg(&up[off]) << 7) | (vv & 127);
}

// ---------------------------------------------------------------------------
// setup: weight convert + transpose, all 66 slots in one kernel
// ---------------------------------------------------------------------------
__global__ void wsplit_all_kernel(const float* __restrict__ ic_w1,
                                  const float* __restrict__ if_w1,
                                  const float* __restrict__ ctr_w,
                                  const float* __restrict__ pre_w,
                                  const float* __restrict__ suc_w,
                                  const float* __restrict__ left_w,
                                  const float* __restrict__ right_w,
                                  const float* __restrict__ ctr2_w) {
  int idx = blockIdx.x * 256 + threadIdx.x;  // NSLOT * 16384
  int slot = idx >> 14, r = idx & 16383;
  int c = r >> 7, k = r & 127;
  const float* src; int m;
  if (slot < 1)       { src = ic_w1;  m = 0; }
  else if (slot < 2)  { src = if_w1;  m = 0; }
  else if (slot < 6)  { src = ctr_w;  m = slot - 2; }
  else if (slot < 30) { src = pre_w;  m = slot - 6; }
  else if (slot < 54) { src = suc_w;  m = slot - 30; }
  else if (slot < 58) { src = left_w; m = slot - 54; }
  else if (slot < 62) { src = right_w; m = slot - 58; }
  else                { src = ctr2_w; m = slot - 62; }
  float w = src[(size_t)m * CC + k * 128 + c];
  g_Wh[(size_t)slot * CC + r] = __float2half_rn(w);
}

// ---------------------------------------------------------------------------
extern "C" void kernel_launch(void* const* d_in, const int* in_sizes, int n_in,
                              void* d_out, int out_size) {
  const float* ctrs   = (const float*)d_in[0];
  const float* feats  = (const float*)d_in[1];
  const int*   pre_u  = (const int*)d_in[2];
  const int*   pre_v  = (const int*)d_in[3];
  const int*   suc_u  = (const int*)d_in[4];
  const int*   suc_v  = (const int*)d_in[5];
  const int*   left_u = (const int*)d_in[6];
  const int*   left_v = (const int*)d_in[7];
  const int*   right_u= (const int*)d_in[8];
  const int*   right_v= (const int*)d_in[9];
  const float* ic_w0  = (const float*)d_in[10];
  const float* ic_b0  = (const float*)d_in[11];
  const float* ic_w1  = (const float*)d_in[12];
  const float* ic_g   = (const float*)d_in[13];
  const float* ic_bt  = (const float*)d_in[14];
  const float* if_w0  = (const float*)d_in[15];
  const float* if_b0  = (const float*)d_in[16];
  const float* if_w1  = (const float*)d_in[17];
  const float* if_g   = (const float*)d_in[18];
  const float* if_bt  = (const float*)d_in[19];
  const float* ctr_w  = (const float*)d_in[20];
  const float* pre_w  = (const float*)d_in[21];
  const float* suc_w  = (const float*)d_in[22];
  const float* left_w = (const float*)d_in[23];
  const float* right_w= (const float*)d_in[24];
  const float* norm_g = (const float*)d_in[25];
  const float* norm_b = (const float*)d_in[26];
  const float* ctr2_w = (const float*)d_in[27];
  const float* ctr2_g = (const float*)d_in[28];
  const float* ctr2_b = (const float*)d_in[29];
  float* out = (float*)d_out;

  float *FT, *TP;
  __half *AA, *WH;
  cudaGetSymbolAddress((void**)&FT, g_feat);
  cudaGetSymbolAddress((void**)&TP, g_temp);
  cudaGetSymbolAddress((void**)&AA, g_A);
  cudaGetSymbolAddress((void**)&WH, g_Wh);

  cudaFuncSetAttribute(input_fused_kernel,
                       cudaFuncAttributeMaxDynamicSharedMemorySize,
                       SMEM_INPUT);
  cudaFuncSetAttribute(gn_gemm_gn_kernel,
                       cudaFuncAttributeMaxDynamicSharedMemorySize, SMEM_TAIL);
  cudaFuncSetAttribute(fused_block_kernel,
                       cudaFuncAttributeMaxDynamicSharedMemorySize, SMEM_FUSED);

  const int GEMM_GRID = N / 128;
  const int ZG = (NLS * NT + 255) / 256;
  const int EG = (12 * E + 255) / 256;

  // ---- setup: weight convert (1) + edge sort (4) ----
  wsplit_all_kernel<<<NSLOT * 64, 256>>>(ic_w1, if_w1, ctr_w, pre_w, suc_w,
                                         left_w, right_w, ctr2_w);
  zero_cnt_kernel<<<ZG, 256>>>();
  hist_all_kernel<<<EG, 256>>>(pre_v, suc_v);
  prefix_kernel<<<NLS, NT>>>();
  fill_all_kernel<<<EG, 256>>>(pre_u, pre_v, suc_u, suc_v);

  // ---- Input stage: 1 fused kernel ----
  input_fused_kernel<<<GEMM_GRID, 256, SMEM_INPUT>>>(
      ctrs, ic_w0, ic_b0, feats, if_w0, if_b0, WH, ic_g, ic_bt, if_g, if_bt,
      FT, AA, TP);

  // ---- 4 fusion blocks: 2 kernels each ----
  for (int i = 0; i < NB; ++i) {
    fused_block_kernel<<<GEMM_GRID, 256, SMEM_FUSED>>>(AA, i, TP, left_u,
                                                       left_v, right_u,
                                                       right_v);

    if (i == NB - 1) {
      gn_gemm_gn_kernel<<<GEMM_GRID, 256, SMEM_TAIL>>>(
          TP, norm_g + (size_t)i * C, norm_b + (size_t)i * C,
          WH + (size_t)(62 + i) * CC, ctr2_g + (size_t)i * C,
          ctr2_b + (size_t)i * C, FT, out, nullptr, nullptr);
    } else {
      gn_gemm_gn_kernel<<<GEMM_GRID, 256, SMEM_TAIL>>>(
          TP, norm_g + (size_t)i * C, norm_b + (size_t)i * C,
          WH + (size_t)(62 + i) * CC, ctr2_g + (size_t)i * C,
          ctr2_b + (size_t)i * C, FT, FT, AA, TP);
    }
  }
}